// round 2
// baseline (speedup 1.0000x reference)
#include <cuda_runtime.h>
#include <cuda_fp16.h>
#include <math.h>
#include <stdint.h>

#define BATCH  2
#define SEQ    2048
#define DMODEL 2048
#define NH     16
#define NKV    8
#define HD     128

// ---------------------------------------------------------------------------
// Scratch (device globals; no allocation allowed)
// ---------------------------------------------------------------------------
__device__ __half g_q[(size_t)BATCH * NH  * SEQ * HD];   // [b][h][s][d], rope'd + scaled
__device__ __half g_k[(size_t)BATCH * NKV * SEQ * HD];   // [b][kv][s][d], rope'd
__device__ __half g_v[(size_t)BATCH * NKV * SEQ * HD];   // [b][kv][s][d]
__device__ float  g_o[(size_t)BATCH * SEQ * NH * HD];    // [b*S + s][h*hd + d] fp32
__device__ float  g_cos[SEQ * (HD / 2)];
__device__ float  g_sin[SEQ * (HD / 2)];

// ---------------------------------------------------------------------------
// Helpers
// ---------------------------------------------------------------------------
__device__ __forceinline__ uint32_t pack_half2(float a, float b) {
  __half2 h = __floats2half2_rn(a, b);
  return *reinterpret_cast<uint32_t*>(&h);
}

// mma.sync m16n8k16 fp16 -> fp32
#define MMA_16816(C, A, B0, B1)                                              \
  asm volatile(                                                              \
      "mma.sync.aligned.m16n8k16.row.col.f32.f16.f16.f32 "                   \
      "{%0,%1,%2,%3}, {%4,%5,%6,%7}, {%8,%9}, {%0,%1,%2,%3};\n"              \
      : "+f"((C)[0]), "+f"((C)[1]), "+f"((C)[2]), "+f"((C)[3])               \
      : "r"((A)[0]), "r"((A)[1]), "r"((A)[2]), "r"((A)[3]),                  \
        "r"(B0), "r"(B1))

// ---------------------------------------------------------------------------
// RoPE tables
// ---------------------------------------------------------------------------
__global__ void rope_init_kernel() {
  int idx = blockIdx.x * blockDim.x + threadIdx.x;
  if (idx < SEQ * (HD / 2)) {
    int s = idx >> 6;
    int i = idx & 63;
    float inv = (float)pow(10000.0, -(double)(2 * i) / (double)HD);
    float a = (float)s * inv;
    g_cos[idx] = cosf(a);
    g_sin[idx] = sinf(a);
  }
}

// ---------------------------------------------------------------------------
// Split-fp16 GEMM: C[4096, N] = A[4096, 2048] @ W[2048, N], both fp32 inputs.
// A = Ah + Al, W = Wh + Wl (fp16 hi + fp16 residual); C ≈ AhWh + AhWl + AlWh.
// MODE 0: Q (rope + 1/sqrt(hd), -> g_q fp16)
// MODE 1: K (rope, -> g_k fp16)
// MODE 2: V (-> g_v fp16)
// MODE 3: output projection (-> out fp32)
// BM=128, BN=64, BK=32, 256 threads (8 warps x 16 rows each)
// ---------------------------------------------------------------------------
template <int MODE>
__global__ __launch_bounds__(256) void gemm_split_kernel(
    const float* __restrict__ A, const float* __restrict__ W,
    float* __restrict__ out, int N) {
  __shared__ __align__(16) __half Ah[128][36];
  __shared__ __align__(16) __half Al[128][36];
  __shared__ __align__(8)  __half Bh[64][36];
  __shared__ __align__(8)  __half Bl[64][36];

  const int tid  = threadIdx.x;
  const int wid  = tid >> 5;
  const int lane = tid & 31;
  const int g    = lane >> 2;   // row group 0..7
  const int q4   = lane & 3;    // col/k group 0..3
  const int m0   = blockIdx.y * 128;
  const int n0   = blockIdx.x * 64;

  float c[8][4];
#pragma unroll
  for (int i = 0; i < 8; i++)
#pragma unroll
    for (int j = 0; j < 4; j++) c[i][j] = 0.f;

  for (int k0 = 0; k0 < DMODEL; k0 += 32) {
    // A tile: 128 x 32 fp32 -> hi/lo fp16 smem
#pragma unroll
    for (int j = 0; j < 4; j++) {
      int i   = j * 256 + tid;
      int row = i >> 3;
      int f4  = i & 7;
      float4 v = *(const float4*)(A + (size_t)(m0 + row) * DMODEL + k0 + f4 * 4);
      float e[4] = {v.x, v.y, v.z, v.w};
      __half hh[4], hl[4];
#pragma unroll
      for (int t = 0; t < 4; t++) {
        hh[t] = __float2half_rn(e[t]);
        hl[t] = __float2half_rn(e[t] - __half2float(hh[t]));
      }
      *(__half2*)&Ah[row][f4 * 4]     = __halves2half2(hh[0], hh[1]);
      *(__half2*)&Ah[row][f4 * 4 + 2] = __halves2half2(hh[2], hh[3]);
      *(__half2*)&Al[row][f4 * 4]     = __halves2half2(hl[0], hl[1]);
      *(__half2*)&Al[row][f4 * 4 + 2] = __halves2half2(hl[2], hl[3]);
    }
    // B tile: 32 x 64 fp32 -> transposed hi/lo fp16 smem [n][k]
#pragma unroll
    for (int j = 0; j < 2; j++) {
      int i  = j * 256 + tid;
      int kk = i >> 4;
      int f4 = i & 15;
      float4 v = *(const float4*)(W + (size_t)(k0 + kk) * N + n0 + f4 * 4);
      float e[4] = {v.x, v.y, v.z, v.w};
#pragma unroll
      for (int t = 0; t < 4; t++) {
        __half hh = __float2half_rn(e[t]);
        __half hl = __float2half_rn(e[t] - __half2float(hh));
        Bh[f4 * 4 + t][kk] = hh;
        Bl[f4 * 4 + t][kk] = hl;
      }
    }
    __syncthreads();

#pragma unroll
    for (int kt = 0; kt < 2; kt++) {
      int kb = kt * 16 + q4 * 2;
      uint32_t ah[4], al[4];
      ah[0] = *(const uint32_t*)&Ah[wid * 16 + g][kb];
      ah[1] = *(const uint32_t*)&Ah[wid * 16 + g + 8][kb];
      ah[2] = *(const uint32_t*)&Ah[wid * 16 + g][kb + 8];
      ah[3] = *(const uint32_t*)&Ah[wid * 16 + g + 8][kb + 8];
      al[0] = *(const uint32_t*)&Al[wid * 16 + g][kb];
      al[1] = *(const uint32_t*)&Al[wid * 16 + g + 8][kb];
      al[2] = *(const uint32_t*)&Al[wid * 16 + g][kb + 8];
      al[3] = *(const uint32_t*)&Al[wid * 16 + g + 8][kb + 8];
#pragma unroll
      for (int nt = 0; nt < 8; nt++) {
        uint32_t bh0 = *(const uint32_t*)&Bh[nt * 8 + g][kb];
        uint32_t bh1 = *(const uint32_t*)&Bh[nt * 8 + g][kb + 8];
        uint32_t bl0 = *(const uint32_t*)&Bl[nt * 8 + g][kb];
        uint32_t bl1 = *(const uint32_t*)&Bl[nt * 8 + g][kb + 8];
        MMA_16816(c[nt], ah, bh0, bh1);
        MMA_16816(c[nt], ah, bl0, bl1);
        MMA_16816(c[nt], al, bh0, bh1);
      }
    }
    __syncthreads();
  }

  // Epilogue
  const float qscale = 0.08838834764831845f;  // 1/sqrt(128)
#pragma unroll
  for (int nt = 0; nt < 8; nt++) {
    int col = n0 + nt * 8 + q4 * 2;
    if (MODE == 3) {
      int row = m0 + wid * 16 + g;
      *(float2*)&out[(size_t)row * DMODEL + col]       = make_float2(c[nt][0], c[nt][1]);
      *(float2*)&out[(size_t)(row + 8) * DMODEL + col] = make_float2(c[nt][2], c[nt][3]);
    } else {
      int head = col >> 7;
      int d    = col & 127;
#pragma unroll
      for (int hh = 0; hh < 2; hh++) {
        int row = m0 + wid * 16 + g + hh * 8;
        int b   = row >> 11;
        int s   = row & 2047;
        float v0 = c[nt][hh * 2];
        float v1 = c[nt][hh * 2 + 1];
        if (MODE != 2) {
          int i    = d >> 1;
          float cs = g_cos[s * 64 + i];
          float sn = g_sin[s * 64 + i];
          float r0 = v0 * cs - v1 * sn;
          float r1 = v0 * sn + v1 * cs;
          v0 = r0; v1 = r1;
          if (MODE == 0) { v0 *= qscale; v1 *= qscale; }
        }
        __half* dst;
        if (MODE == 0)
          dst = &g_q[(((size_t)(b * NH + head)) * SEQ + s) * HD + d];
        else if (MODE == 1)
          dst = &g_k[(((size_t)(b * NKV + head)) * SEQ + s) * HD + d];
        else
          dst = &g_v[(((size_t)(b * NKV + head)) * SEQ + s) * HD + d];
        *(__half2*)dst = __floats2half2_rn(v0, v1);
      }
    }
  }
}

// ---------------------------------------------------------------------------
// Flash attention: one block = (qtile of 64 rows, head h, batch b)
// 128 threads = 4 warps x 16 rows. KV chunks of 64. Online softmax.
// ---------------------------------------------------------------------------
__global__ __launch_bounds__(128) void attn_kernel(const int* __restrict__ causal_flag) {
  __shared__ __align__(16) __half Ks[64][136];   // K chunk [seq][d] (also Q staging)
  __shared__ __align__(16) __half Vs[128][66];   // V chunk transposed [d][seq]

  const int tid  = threadIdx.x;
  const int wid  = tid >> 5;
  const int lane = tid & 31;
  const int g    = lane >> 2;
  const int q4   = lane & 3;
  const int qtile = blockIdx.x;
  const int h     = blockIdx.y;
  const int b     = blockIdx.z;
  const int kv    = h >> 1;            // G = NH/NKV = 2
  const int qbase = qtile * 64;
  const int causal = *causal_flag;

  // Stage Q tile into Ks, extract A fragments (Q pre-scaled by 1/sqrt(hd))
  const __half* qp = g_q + (((size_t)(b * NH + h)) * SEQ + qbase) * HD;
#pragma unroll
  for (int j = 0; j < 8; j++) {
    int i   = j * 128 + tid;
    int row = i >> 4;
    int seg = i & 15;
    *(uint4*)&Ks[row][seg * 8] = *(const uint4*)(qp + row * HD + seg * 8);
  }
  __syncthreads();
  uint32_t qa[8][4];
#pragma unroll
  for (int kt = 0; kt < 8; kt++) {
    int kb = kt * 16 + q4 * 2;
    qa[kt][0] = *(const uint32_t*)&Ks[wid * 16 + g][kb];
    qa[kt][1] = *(const uint32_t*)&Ks[wid * 16 + g + 8][kb];
    qa[kt][2] = *(const uint32_t*)&Ks[wid * 16 + g][kb + 8];
    qa[kt][3] = *(const uint32_t*)&Ks[wid * 16 + g + 8][kb + 8];
  }

  float o[16][4];
#pragma unroll
  for (int i = 0; i < 16; i++)
#pragma unroll
    for (int j = 0; j < 4; j++) o[i][j] = 0.f;
  float m0 = -1e30f, m1 = -1e30f, l0 = 0.f, l1 = 0.f;

  const int jend = causal ? (qbase + 64) : SEQ;
  const __half* kbp = g_k + ((size_t)(b * NKV + kv)) * SEQ * HD;
  const __half* vbp = g_v + ((size_t)(b * NKV + kv)) * SEQ * HD;
  const int row0 = qbase + wid * 16 + g;
  const int row1 = row0 + 8;

  for (int j0 = 0; j0 < jend; j0 += 64) {
    __syncthreads();  // protect previous chunk's smem reads / Q frag extraction
    // K chunk [64][128]
#pragma unroll
    for (int j = 0; j < 8; j++) {
      int i   = j * 128 + tid;
      int row = i >> 4;
      int seg = i & 15;
      *(uint4*)&Ks[row][seg * 8] =
          *(const uint4*)(kbp + (size_t)(j0 + row) * HD + seg * 8);
    }
    // V chunk transposed -> Vs[d][seq]
#pragma unroll
    for (int j = 0; j < 8; j++) {
      int i   = j * 128 + tid;
      int row = i >> 4;
      int seg = i & 15;
      uint4 u = *(const uint4*)(vbp + (size_t)(j0 + row) * HD + seg * 8);
      const __half* hv = (const __half*)&u;
#pragma unroll
      for (int e = 0; e < 8; e++) Vs[seg * 8 + e][row] = hv[e];
    }
    __syncthreads();

    // S = Q @ K^T (64x64 per block, 16x64 per warp)
    float sc[8][4];
#pragma unroll
    for (int i = 0; i < 8; i++)
#pragma unroll
      for (int j = 0; j < 4; j++) sc[i][j] = 0.f;
#pragma unroll
    for (int kt = 0; kt < 8; kt++) {
      int kb = kt * 16 + q4 * 2;
#pragma unroll
      for (int nt = 0; nt < 8; nt++) {
        uint32_t b0 = *(const uint32_t*)&Ks[nt * 8 + g][kb];
        uint32_t b1 = *(const uint32_t*)&Ks[nt * 8 + g][kb + 8];
        MMA_16816(sc[nt], qa[kt], b0, b1);
      }
    }

    // Causal mask: only the diagonal chunk needs it
    if (causal && j0 == qbase) {
#pragma unroll
      for (int nt = 0; nt < 8; nt++) {
        int col = j0 + nt * 8 + q4 * 2;
        if (col     > row0) sc[nt][0] = -1e30f;
        if (col + 1 > row0) sc[nt][1] = -1e30f;
        if (col     > row1) sc[nt][2] = -1e30f;
        if (col + 1 > row1) sc[nt][3] = -1e30f;
      }
    }

    // Online softmax (rows g and g+8 per thread; 4-lane groups share a row)
    float r0 = -1e30f, r1 = -1e30f;
#pragma unroll
    for (int nt = 0; nt < 8; nt++) {
      r0 = fmaxf(r0, fmaxf(sc[nt][0], sc[nt][1]));
      r1 = fmaxf(r1, fmaxf(sc[nt][2], sc[nt][3]));
    }
    r0 = fmaxf(r0, __shfl_xor_sync(0xffffffffu, r0, 1));
    r0 = fmaxf(r0, __shfl_xor_sync(0xffffffffu, r0, 2));
    r1 = fmaxf(r1, __shfl_xor_sync(0xffffffffu, r1, 1));
    r1 = fmaxf(r1, __shfl_xor_sync(0xffffffffu, r1, 2));
    float mn0 = fmaxf(m0, r0), mn1 = fmaxf(m1, r1);
    float sf0 = __expf(m0 - mn0), sf1 = __expf(m1 - mn1);
    m0 = mn0; m1 = mn1;
    float s0 = 0.f, s1 = 0.f;
#pragma unroll
    for (int nt = 0; nt < 8; nt++) {
      sc[nt][0] = __expf(sc[nt][0] - mn0);
      sc[nt][1] = __expf(sc[nt][1] - mn0);
      sc[nt][2] = __expf(sc[nt][2] - mn1);
      sc[nt][3] = __expf(sc[nt][3] - mn1);
      s0 += sc[nt][0] + sc[nt][1];
      s1 += sc[nt][2] + sc[nt][3];
    }
    s0 += __shfl_xor_sync(0xffffffffu, s0, 1);
    s0 += __shfl_xor_sync(0xffffffffu, s0, 2);
    s1 += __shfl_xor_sync(0xffffffffu, s1, 1);
    s1 += __shfl_xor_sync(0xffffffffu, s1, 2);
    l0 = l0 * sf0 + s0;
    l1 = l1 * sf1 + s1;
#pragma unroll
    for (int i = 0; i < 16; i++) {
      o[i][0] *= sf0; o[i][1] *= sf0;
      o[i][2] *= sf1; o[i][3] *= sf1;
    }

    // P (C-layout) reinterpreted as A fragments: ntile pair (2kt,2kt+1) = ktile kt
    uint32_t pa[4][4];
#pragma unroll
    for (int kt = 0; kt < 4; kt++) {
      pa[kt][0] = pack_half2(sc[2 * kt][0], sc[2 * kt][1]);
      pa[kt][1] = pack_half2(sc[2 * kt][2], sc[2 * kt][3]);
      pa[kt][2] = pack_half2(sc[2 * kt + 1][0], sc[2 * kt + 1][1]);
      pa[kt][3] = pack_half2(sc[2 * kt + 1][2], sc[2 * kt + 1][3]);
    }

    // O += P @ V  (16 x 128 per warp)
#pragma unroll
    for (int kt = 0; kt < 4; kt++) {
      int kb = kt * 16 + q4 * 2;
#pragma unroll
      for (int nt = 0; nt < 16; nt++) {
        uint32_t b0 = *(const uint32_t*)&Vs[nt * 8 + g][kb];
        uint32_t b1 = *(const uint32_t*)&Vs[nt * 8 + g][kb + 8];
        MMA_16816(o[nt], pa[kt], b0, b1);
      }
    }
  }

  // Normalize and store O (fp32) to g_o[(b*S + s)][h*hd + d]
  float inv0 = 1.f / l0, inv1 = 1.f / l1;
#pragma unroll
  for (int nt = 0; nt < 16; nt++) {
    int d = nt * 8 + q4 * 2;
    float* p0 = &g_o[((size_t)(b * SEQ + row0)) * (NH * HD) + h * HD + d];
    float* p1 = &g_o[((size_t)(b * SEQ + row1)) * (NH * HD) + h * HD + d];
    *(float2*)p0 = make_float2(o[nt][0] * inv0, o[nt][1] * inv0);
    *(float2*)p1 = make_float2(o[nt][2] * inv1, o[nt][3] * inv1);
  }
}

// ---------------------------------------------------------------------------
// Launch
// ---------------------------------------------------------------------------
extern "C" void kernel_launch(void* const* d_in, const int* in_sizes, int n_in,
                              void* d_out, int out_size) {
  const float* x  = (const float*)d_in[0];
  const float* Wq = (const float*)d_in[1];
  const float* Wk = (const float*)d_in[2];
  const float* Wv = (const float*)d_in[3];
  const float* Wo = (const float*)d_in[4];
  const int* is_causal = (const int*)d_in[5];
  float* out = (float*)d_out;

  float* g_o_ptr = nullptr;
  cudaGetSymbolAddress((void**)&g_o_ptr, g_o);

  rope_init_kernel<<<(SEQ * 64 + 255) / 256, 256>>>();

  gemm_split_kernel<0><<<dim3((NH * HD) / 64, (BATCH * SEQ) / 128), 256>>>(
      x, Wq, nullptr, NH * HD);
  gemm_split_kernel<1><<<dim3((NKV * HD) / 64, (BATCH * SEQ) / 128), 256>>>(
      x, Wk, nullptr, NKV * HD);
  gemm_split_kernel<2><<<dim3((NKV * HD) / 64, (BATCH * SEQ) / 128), 256>>>(
      x, Wv, nullptr, NKV * HD);

  attn_kernel<<<dim3(SEQ / 64, NH, BATCH), 128>>>(is_causal);

  gemm_split_kernel<3><<<dim3(DMODEL / 64, (BATCH * SEQ) / 128), 256>>>(
      g_o_ptr, Wo, out, DMODEL);
}